// round 1
// baseline (speedup 1.0000x reference)
#include <cuda_runtime.h>
#include <math.h>

namespace {
constexpr int H        = 128;
constexpr int PITCH    = 132;   // padded shared row: keeps LDS.128 conflict-free, 16B aligned
constexpr int NNODE    = 13;
constexpr int NJN      = 12;
constexpr int TT       = 3;
constexpr int OBSW     = 47;
constexpr int OBS_LEN  = TT * OBSW;  // 141
constexpr int GPB      = 8;          // graphs per block (1 warp per graph)
constexpr int NTHREADS = 256;
constexpr int NLAYER   = 3;
constexpr int BASE_F   = 33;
constexpr int JOINT_F  = 9;

struct Smem {
    float wrel[H * PITCH];        // [h][o] transposed  (67.6 KB)
    float wroot[H * PITCH];       // [h][o] transposed  (67.6 KB)
    float web[BASE_F * PITCH];    // [f][o]             (17.4 KB)
    float wej[JOINT_F * PITCH];   // [f][o]             ( 4.8 KB)
    float xs[GPB][NNODE][H];      //                    (53.2 KB)
    float obs_s[GPB][144];        //                    ( 4.6 KB)
    float beb[H];
    float bej[H];
    float brel[NLAYER][H];
    float wdec[H];
    float bdec;
};

__device__ __forceinline__ float elu1(float v) { return v > 0.f ? v : expm1f(v); }
__device__ __forceinline__ float4 elu4(float4 v) {
    return make_float4(elu1(v.x), elu1(v.y), elu1(v.z), elu1(v.w));
}
__device__ __forceinline__ float4 add4(float4 a, float4 b) {
    return make_float4(a.x + b.x, a.y + b.y, a.z + b.z, a.w + b.w);
}
} // namespace

#define FMA4(Y, A, W)                                                     \
    do {                                                                  \
        (Y).x = fmaf((A), (W).x, (Y).x);                                  \
        (Y).y = fmaf((A), (W).y, (Y).y);                                  \
        (Y).z = fmaf((A), (W).z, (Y).z);                                  \
        (Y).w = fmaf((A), (W).w, (Y).w);                                  \
    } while (0)

// one node's contribution for 4 h-values: y[n] += agg*Wrel + x*Wroot
#define GSTEP(n, AGG)                                                     \
    do {                                                                  \
        float4 a_ = (AGG);                                                \
        FMA4(y[n], a_.x, wr0);  FMA4(y[n], xv[n].x, wo0);                 \
        FMA4(y[n], a_.y, wr1);  FMA4(y[n], xv[n].y, wo1);                 \
        FMA4(y[n], a_.z, wr2);  FMA4(y[n], xv[n].z, wo2);                 \
        FMA4(y[n], a_.w, wr3);  FMA4(y[n], xv[n].w, wo3);                 \
    } while (0)

__global__ __launch_bounds__(NTHREADS) void gnn_fused_kernel(
    const float* __restrict__ obs,
    const float* __restrict__ We_b, const float* __restrict__ be_b,
    const float* __restrict__ We_j, const float* __restrict__ be_j,
    const float* __restrict__ W_rel, const float* __restrict__ W_root,
    const float* __restrict__ b_rel,
    const float* __restrict__ W_dec, const float* __restrict__ b_dec,
    float* __restrict__ out, int B)
{
    extern __shared__ char smem_raw[];
    Smem& s = *reinterpret_cast<Smem*>(smem_raw);
    const int tid  = threadIdx.x;
    const int lane = tid & 31;
    const int warp = tid >> 5;

    // ---- stage encoder weights (transposed), biases ----
    for (int i = tid; i < H * BASE_F; i += NTHREADS) {
        int o = i / BASE_F, f = i - o * BASE_F;
        s.web[f * PITCH + o] = We_b[i];
    }
    for (int i = tid; i < H * JOINT_F; i += NTHREADS) {
        int o = i / JOINT_F, f = i - o * JOINT_F;
        s.wej[f * PITCH + o] = We_j[i];
    }
    if (tid < H) {
        s.beb[tid]  = be_b[tid];
        s.bej[tid]  = be_j[tid];
        s.wdec[tid] = W_dec[tid];
    }
    for (int i = tid; i < NLAYER * H; i += NTHREADS)
        (&s.brel[0][0])[i] = b_rel[i];
    if (tid == 0) s.bdec = b_dec[0];

    const int  b      = blockIdx.x * GPB + warp;
    const bool active = (b < B);
    if (active) {
        for (int i = lane; i < OBS_LEN; i += 32)
            s.obs_s[warp][i] = obs[b * OBS_LEN + i];
    }
    __syncthreads();

    const int o0 = lane * 4;

    // ---------------- encoders ----------------
    if (active) {
        const int BIDX[11] = {0, 1, 2, 3, 4, 5, 6, 7, 8, 45, 46};
        // base node (node 0): base_feat[f=t*11+i] = obs[t*47 + BIDX[i]]
        float4 acc = *reinterpret_cast<const float4*>(&s.beb[o0]);
        #pragma unroll
        for (int t = 0; t < TT; t++) {
            #pragma unroll
            for (int i = 0; i < 11; i++) {
                float  feat = s.obs_s[warp][t * OBSW + BIDX[i]];
                float4 wb   = *reinterpret_cast<const float4*>(&s.web[(t * 11 + i) * PITCH + o0]);
                FMA4(acc, feat, wb);
            }
        }
        *reinterpret_cast<float4*>(&s.xs[warp][0][o0]) = elu4(acc);

        // joint nodes 1..12: joint_feat[j, f=t*3+c] = obs[t*47 + 9 + c*12 + j]
        float4 aj[NJN];
        float4 bj = *reinterpret_cast<const float4*>(&s.bej[o0]);
        #pragma unroll
        for (int j = 0; j < NJN; j++) aj[j] = bj;
        #pragma unroll
        for (int f = 0; f < JOINT_F; f++) {
            int    t  = f / 3, c = f % 3;
            float4 wj = *reinterpret_cast<const float4*>(&s.wej[f * PITCH + o0]);
            #pragma unroll
            for (int j = 0; j < NJN; j++) {
                float feat = s.obs_s[warp][t * OBSW + 9 + c * 12 + j];
                FMA4(aj[j], feat, wj);
            }
        }
        #pragma unroll
        for (int j = 0; j < NJN; j++)
            *reinterpret_cast<float4*>(&s.xs[warp][1 + j][o0]) = elu4(aj[j]);
    }

    // ---------------- GraphConv layers ----------------
    for (int l = 0; l < NLAYER; l++) {
        __syncthreads();  // previous layer's sW readers done / xs writers done
        {
            const float* wr = W_rel  + l * H * H;
            const float* wo = W_root + l * H * H;
            for (int i = tid; i < H * H; i += NTHREADS) {
                int o = i >> 7, h = i & (H - 1);
                s.wrel[h * PITCH + o]  = wr[i];
                s.wroot[h * PITCH + o] = wo[i];
            }
        }
        __syncthreads();

        if (active) {
            float4 y[NNODE];
            #pragma unroll
            for (int n = 0; n < NNODE; n++) y[n] = make_float4(0.f, 0.f, 0.f, 0.f);

            #pragma unroll 1
            for (int h0 = 0; h0 < H; h0 += 4) {
                float4 xv[NNODE];
                #pragma unroll
                for (int n = 0; n < NNODE; n++)
                    xv[n] = *reinterpret_cast<const float4*>(&s.xs[warp][n][h0]);

                float4 wr0 = *reinterpret_cast<const float4*>(&s.wrel[(h0 + 0) * PITCH + o0]);
                float4 wr1 = *reinterpret_cast<const float4*>(&s.wrel[(h0 + 1) * PITCH + o0]);
                float4 wr2 = *reinterpret_cast<const float4*>(&s.wrel[(h0 + 2) * PITCH + o0]);
                float4 wr3 = *reinterpret_cast<const float4*>(&s.wrel[(h0 + 3) * PITCH + o0]);
                float4 wo0 = *reinterpret_cast<const float4*>(&s.wroot[(h0 + 0) * PITCH + o0]);
                float4 wo1 = *reinterpret_cast<const float4*>(&s.wroot[(h0 + 1) * PITCH + o0]);
                float4 wo2 = *reinterpret_cast<const float4*>(&s.wroot[(h0 + 2) * PITCH + o0]);
                float4 wo3 = *reinterpret_cast<const float4*>(&s.wroot[(h0 + 3) * PITCH + o0]);

                // fixed tree in-neighbors (matches src/dst constants in the dataset)
                GSTEP(0,  add4(add4(xv[1], xv[4]), add4(xv[7], xv[10])));
                GSTEP(1,  add4(xv[0],  xv[2]));
                GSTEP(2,  add4(xv[1],  xv[3]));
                GSTEP(3,  xv[2]);
                GSTEP(4,  add4(xv[0],  xv[5]));
                GSTEP(5,  add4(xv[4],  xv[6]));
                GSTEP(6,  xv[5]);
                GSTEP(7,  add4(xv[0],  xv[8]));
                GSTEP(8,  add4(xv[7],  xv[9]));
                GSTEP(9,  xv[8]);
                GSTEP(10, add4(xv[0],  xv[11]));
                GSTEP(11, add4(xv[10], xv[12]));
                GSTEP(12, xv[11]);
            }

            float4 br = *reinterpret_cast<const float4*>(&s.brel[l][o0]);
            #pragma unroll
            for (int n = 0; n < NNODE; n++) {
                float4 v = add4(y[n], br);
                *reinterpret_cast<float4*>(&s.xs[warp][n][o0]) = elu4(v);
            }
        }
    }

    // ---------------- decoder ----------------
    if (active) {
        __syncwarp();
        float4 wd = *reinterpret_cast<const float4*>(&s.wdec[o0]);
        float  bd = s.bdec;
        #pragma unroll
        for (int j = 0; j < NJN; j++) {
            float4 xv = *reinterpret_cast<const float4*>(&s.xs[warp][1 + j][o0]);
            float  p  = xv.x * wd.x + xv.y * wd.y + xv.z * wd.z + xv.w * wd.w;
            #pragma unroll
            for (int off = 16; off > 0; off >>= 1)
                p += __shfl_xor_sync(0xffffffffu, p, off);
            if (lane == 0) out[b * NJN + j] = p + bd;
        }
    }
}

extern "C" void kernel_launch(void* const* d_in, const int* in_sizes, int n_in,
                              void* d_out, int out_size)
{
    const float* obs    = (const float*)d_in[0];
    const float* We_b   = (const float*)d_in[1];
    const float* be_b   = (const float*)d_in[2];
    const float* We_j   = (const float*)d_in[3];
    const float* be_j   = (const float*)d_in[4];
    const float* W_rel  = (const float*)d_in[5];
    const float* W_root = (const float*)d_in[6];
    const float* b_rel  = (const float*)d_in[7];
    const float* W_dec  = (const float*)d_in[8];
    const float* b_dec  = (const float*)d_in[9];
    float*       out    = (float*)d_out;

    const int B    = in_sizes[0] / OBS_LEN;
    const int grid = (B + GPB - 1) / GPB;
    const size_t shmem = sizeof(Smem);

    cudaFuncSetAttribute(gnn_fused_kernel,
                         cudaFuncAttributeMaxDynamicSharedMemorySize, (int)shmem);

    gnn_fused_kernel<<<grid, NTHREADS, shmem>>>(
        obs, We_b, be_b, We_j, be_j, W_rel, W_root, b_rel, W_dec, b_dec, out, B);
}

// round 2
// speedup vs baseline: 1.0009x; 1.0009x over previous
#include <cuda_runtime.h>
#include <math.h>

namespace {
constexpr int H        = 128;
constexpr int PITCH    = 132;   // padded shared row: keeps LDS.128 conflict-free, 16B aligned
constexpr int NNODE    = 13;
constexpr int NJN      = 12;
constexpr int TT       = 3;
constexpr int OBSW     = 47;
constexpr int OBS_LEN  = TT * OBSW;  // 141
constexpr int GPB      = 8;          // graphs per block (1 warp per graph)
constexpr int NTHREADS = 256;
constexpr int NLAYER   = 3;
constexpr int BASE_F   = 33;
constexpr int JOINT_F  = 9;

struct Smem {
    float wrel[H * PITCH];        // [h][o] transposed  (67.6 KB)
    float wroot[H * PITCH];       // [h][o] transposed  (67.6 KB)
    float web[BASE_F * PITCH];    // [f][o]             (17.4 KB)
    float wej[JOINT_F * PITCH];   // [f][o]             ( 4.8 KB)
    float xs[GPB][NNODE][H];      //                    (53.2 KB)
    float obs_s[GPB][144];        //                    ( 4.6 KB)
    float beb[H];
    float bej[H];
    float brel[NLAYER][H];
    float wdec[H];
    float bdec;
};

__device__ __forceinline__ float elu1(float v) { return v > 0.f ? v : expm1f(v); }
__device__ __forceinline__ float4 elu4(float4 v) {
    return make_float4(elu1(v.x), elu1(v.y), elu1(v.z), elu1(v.w));
}
__device__ __forceinline__ float4 add4(float4 a, float4 b) {
    return make_float4(a.x + b.x, a.y + b.y, a.z + b.z, a.w + b.w);
}
} // namespace

#define FMA4(Y, A, W)                                                     \
    do {                                                                  \
        (Y).x = fmaf((A), (W).x, (Y).x);                                  \
        (Y).y = fmaf((A), (W).y, (Y).y);                                  \
        (Y).z = fmaf((A), (W).z, (Y).z);                                  \
        (Y).w = fmaf((A), (W).w, (Y).w);                                  \
    } while (0)

// one node's contribution for 4 h-values: y[n] += agg*Wrel + x*Wroot
#define GSTEP(n, AGG)                                                     \
    do {                                                                  \
        float4 a_ = (AGG);                                                \
        FMA4(y[n], a_.x, wr0);  FMA4(y[n], xv[n].x, wo0);                 \
        FMA4(y[n], a_.y, wr1);  FMA4(y[n], xv[n].y, wo1);                 \
        FMA4(y[n], a_.z, wr2);  FMA4(y[n], xv[n].z, wo2);                 \
        FMA4(y[n], a_.w, wr3);  FMA4(y[n], xv[n].w, wo3);                 \
    } while (0)

__global__ __launch_bounds__(NTHREADS) void gnn_fused_kernel(
    const float* __restrict__ obs,
    const float* __restrict__ We_b, const float* __restrict__ be_b,
    const float* __restrict__ We_j, const float* __restrict__ be_j,
    const float* __restrict__ W_rel, const float* __restrict__ W_root,
    const float* __restrict__ b_rel,
    const float* __restrict__ W_dec, const float* __restrict__ b_dec,
    float* __restrict__ out, int B)
{
    extern __shared__ char smem_raw[];
    Smem& s = *reinterpret_cast<Smem*>(smem_raw);
    const int tid  = threadIdx.x;
    const int lane = tid & 31;
    const int warp = tid >> 5;

    // ---- stage encoder weights (transposed), biases ----
    for (int i = tid; i < H * BASE_F; i += NTHREADS) {
        int o = i / BASE_F, f = i - o * BASE_F;
        s.web[f * PITCH + o] = We_b[i];
    }
    for (int i = tid; i < H * JOINT_F; i += NTHREADS) {
        int o = i / JOINT_F, f = i - o * JOINT_F;
        s.wej[f * PITCH + o] = We_j[i];
    }
    if (tid < H) {
        s.beb[tid]  = be_b[tid];
        s.bej[tid]  = be_j[tid];
        s.wdec[tid] = W_dec[tid];
    }
    for (int i = tid; i < NLAYER * H; i += NTHREADS)
        (&s.brel[0][0])[i] = b_rel[i];
    if (tid == 0) s.bdec = b_dec[0];

    const int  b      = blockIdx.x * GPB + warp;
    const bool active = (b < B);
    if (active) {
        for (int i = lane; i < OBS_LEN; i += 32)
            s.obs_s[warp][i] = obs[b * OBS_LEN + i];
    }
    __syncthreads();

    const int o0 = lane * 4;

    // ---------------- encoders ----------------
    if (active) {
        const int BIDX[11] = {0, 1, 2, 3, 4, 5, 6, 7, 8, 45, 46};
        // base node (node 0): base_feat[f=t*11+i] = obs[t*47 + BIDX[i]]
        float4 acc = *reinterpret_cast<const float4*>(&s.beb[o0]);
        #pragma unroll
        for (int t = 0; t < TT; t++) {
            #pragma unroll
            for (int i = 0; i < 11; i++) {
                float  feat = s.obs_s[warp][t * OBSW + BIDX[i]];
                float4 wb   = *reinterpret_cast<const float4*>(&s.web[(t * 11 + i) * PITCH + o0]);
                FMA4(acc, feat, wb);
            }
        }
        *reinterpret_cast<float4*>(&s.xs[warp][0][o0]) = elu4(acc);

        // joint nodes 1..12: joint_feat[j, f=t*3+c] = obs[t*47 + 9 + c*12 + j]
        float4 aj[NJN];
        float4 bj = *reinterpret_cast<const float4*>(&s.bej[o0]);
        #pragma unroll
        for (int j = 0; j < NJN; j++) aj[j] = bj;
        #pragma unroll
        for (int f = 0; f < JOINT_F; f++) {
            int    t  = f / 3, c = f % 3;
            float4 wj = *reinterpret_cast<const float4*>(&s.wej[f * PITCH + o0]);
            #pragma unroll
            for (int j = 0; j < NJN; j++) {
                float feat = s.obs_s[warp][t * OBSW + 9 + c * 12 + j];
                FMA4(aj[j], feat, wj);
            }
        }
        #pragma unroll
        for (int j = 0; j < NJN; j++)
            *reinterpret_cast<float4*>(&s.xs[warp][1 + j][o0]) = elu4(aj[j]);
    }

    // ---------------- GraphConv layers ----------------
    for (int l = 0; l < NLAYER; l++) {
        __syncthreads();  // previous layer's sW readers done / xs writers done
        {
            const float* wr = W_rel  + l * H * H;
            const float* wo = W_root + l * H * H;
            for (int i = tid; i < H * H; i += NTHREADS) {
                int o = i >> 7, h = i & (H - 1);
                s.wrel[h * PITCH + o]  = wr[i];
                s.wroot[h * PITCH + o] = wo[i];
            }
        }
        __syncthreads();

        if (active) {
            float4 y[NNODE];
            #pragma unroll
            for (int n = 0; n < NNODE; n++) y[n] = make_float4(0.f, 0.f, 0.f, 0.f);

            #pragma unroll 1
            for (int h0 = 0; h0 < H; h0 += 4) {
                float4 xv[NNODE];
                #pragma unroll
                for (int n = 0; n < NNODE; n++)
                    xv[n] = *reinterpret_cast<const float4*>(&s.xs[warp][n][h0]);

                float4 wr0 = *reinterpret_cast<const float4*>(&s.wrel[(h0 + 0) * PITCH + o0]);
                float4 wr1 = *reinterpret_cast<const float4*>(&s.wrel[(h0 + 1) * PITCH + o0]);
                float4 wr2 = *reinterpret_cast<const float4*>(&s.wrel[(h0 + 2) * PITCH + o0]);
                float4 wr3 = *reinterpret_cast<const float4*>(&s.wrel[(h0 + 3) * PITCH + o0]);
                float4 wo0 = *reinterpret_cast<const float4*>(&s.wroot[(h0 + 0) * PITCH + o0]);
                float4 wo1 = *reinterpret_cast<const float4*>(&s.wroot[(h0 + 1) * PITCH + o0]);
                float4 wo2 = *reinterpret_cast<const float4*>(&s.wroot[(h0 + 2) * PITCH + o0]);
                float4 wo3 = *reinterpret_cast<const float4*>(&s.wroot[(h0 + 3) * PITCH + o0]);

                // fixed tree in-neighbors (matches src/dst constants in the dataset)
                GSTEP(0,  add4(add4(xv[1], xv[4]), add4(xv[7], xv[10])));
                GSTEP(1,  add4(xv[0],  xv[2]));
                GSTEP(2,  add4(xv[1],  xv[3]));
                GSTEP(3,  xv[2]);
                GSTEP(4,  add4(xv[0],  xv[5]));
                GSTEP(5,  add4(xv[4],  xv[6]));
                GSTEP(6,  xv[5]);
                GSTEP(7,  add4(xv[0],  xv[8]));
                GSTEP(8,  add4(xv[7],  xv[9]));
                GSTEP(9,  xv[8]);
                GSTEP(10, add4(xv[0],  xv[11]));
                GSTEP(11, add4(xv[10], xv[12]));
                GSTEP(12, xv[11]);
            }

            float4 br = *reinterpret_cast<const float4*>(&s.brel[l][o0]);
            #pragma unroll
            for (int n = 0; n < NNODE; n++) {
                float4 v = add4(y[n], br);
                *reinterpret_cast<float4*>(&s.xs[warp][n][o0]) = elu4(v);
            }
        }
    }

    // ---------------- decoder ----------------
    if (active) {
        __syncwarp();
        float4 wd = *reinterpret_cast<const float4*>(&s.wdec[o0]);
        float  bd = s.bdec;
        #pragma unroll
        for (int j = 0; j < NJN; j++) {
            float4 xv = *reinterpret_cast<const float4*>(&s.xs[warp][1 + j][o0]);
            float  p  = xv.x * wd.x + xv.y * wd.y + xv.z * wd.z + xv.w * wd.w;
            #pragma unroll
            for (int off = 16; off > 0; off >>= 1)
                p += __shfl_xor_sync(0xffffffffu, p, off);
            if (lane == 0) out[b * NJN + j] = p + bd;
        }
    }
}

extern "C" void kernel_launch(void* const* d_in, const int* in_sizes, int n_in,
                              void* d_out, int out_size)
{
    const float* obs    = (const float*)d_in[0];
    const float* We_b   = (const float*)d_in[1];
    const float* be_b   = (const float*)d_in[2];
    const float* We_j   = (const float*)d_in[3];
    const float* be_j   = (const float*)d_in[4];
    const float* W_rel  = (const float*)d_in[5];
    const float* W_root = (const float*)d_in[6];
    const float* b_rel  = (const float*)d_in[7];
    const float* W_dec  = (const float*)d_in[8];
    const float* b_dec  = (const float*)d_in[9];
    float*       out    = (float*)d_out;

    const int B    = in_sizes[0] / OBS_LEN;
    const int grid = (B + GPB - 1) / GPB;
    const size_t shmem = sizeof(Smem);

    cudaFuncSetAttribute(gnn_fused_kernel,
                         cudaFuncAttributeMaxDynamicSharedMemorySize, (int)shmem);

    gnn_fused_kernel<<<grid, NTHREADS, shmem>>>(
        obs, We_b, be_b, We_j, be_j, W_rel, W_root, b_rel, W_dec, b_dec, out, B);
}